// round 16
// baseline (speedup 1.0000x reference)
#include <cuda_runtime.h>
#include <cuda_bf16.h>
#include <cstdint>

typedef unsigned long long ull;

#define D_DIM 2048
#define H1 256
#define H2 128
#define NB  384
#define MAX_B 8192

static constexpr size_t B_PLANE = (size_t)NB * D_DIM;

// ---------------- device scratch ----------------
__device__ uint16_t g_Bbf[2 * B_PLANE];            // bf16 planes h,m; rows 256..383 (Wo) used
__device__ float    g_scratch[(size_t)MAX_B * NB]; // [a1(256) | g2 part0(128)]
__device__ float    g_g2p[(size_t)MAX_B * H2];     // g2 part1 (K upper half)
__device__ float    g_u[H2];
__device__ float    g_w[H1];
__device__ float    g_wpart[16][H1];
__device__ float    g_W2T[H2 * H1];

// ---------------- helpers ----------------
__device__ __forceinline__ ull dup2(float x) {
    ull r; asm("mov.b64 %0, {%1, %1};" : "=l"(r) : "f"(x)); return r;
}
__device__ __forceinline__ void fma2(ull &d, ull a, ull b) {
    asm("fma.rn.f32x2 %0, %1, %2, %0;" : "+l"(d) : "l"(a), "l"(b));
}
__device__ __forceinline__ float2 unpack2(ull v) {
    float2 f; asm("mov.b64 {%0, %1}, %2;" : "=f"(f.x), "=f"(f.y) : "l"(v)); return f;
}
__device__ __forceinline__ void cpa16(uint32_t dst, const void* src) {
    asm volatile("cp.async.cg.shared.global [%0], [%1], 16;\n" :: "r"(dst), "l"(src));
}
__device__ __forceinline__ uint32_t s2u(const void* p) {
    uint32_t r; asm("{ .reg .u64 t; cvta.to.shared.u64 t, %1; cvt.u32.u64 %0, t; }" : "=r"(r) : "l"(p)); return r;
}
__device__ __forceinline__ uint32_t packbf(float hi, float lo) {
    uint32_t r; asm("cvt.rn.bf16x2.f32 %0, %1, %2;" : "=r"(r) : "f"(hi), "f"(lo)); return r;
}
__device__ __forceinline__ float bfhi(uint32_t v) { return __uint_as_float(v & 0xFFFF0000u); }
__device__ __forceinline__ float bflo(uint32_t v) { return __uint_as_float(v << 16); }

// 2-way bf16 split of a pair (a = even-k -> lo half, b = odd-k -> hi half)
__device__ __forceinline__ void split2(float a, float b, uint32_t &h, uint32_t &m) {
    h = packbf(b, a);
    float ra = a - bflo(h), rb = b - bfhi(h);
    m = packbf(rb, ra);
}

__device__ __forceinline__ void mma16(float* c, const uint2* A, uint2 b) {
    asm volatile(
        "mma.sync.aligned.m16n8k16.row.col.f32.bf16.bf16.f32 "
        "{%0,%1,%2,%3}, {%4,%5,%6,%7}, {%8,%9}, {%0,%1,%2,%3};"
        : "+f"(c[0]), "+f"(c[1]), "+f"(c[2]), "+f"(c[3])
        : "r"(A[0].x), "r"(A[1].x), "r"(A[0].y), "r"(A[1].y), "r"(b.x), "r"(b.y));
}

// ============================================================
// prep_misc: u = Wo@Wp (bk<128), wpart (bk<144), W2T (bk<160),
//            Wo bf16 planes h,m (bk 160..287). grid 288 x 256
// ============================================================
__global__ __launch_bounds__(256) void prep_misc(
    const float* __restrict__ W1, const float* __restrict__ W2,
    const float* __restrict__ Wo, const float* __restrict__ Wp)
{
    __shared__ float red[256];
    int tid = threadIdx.x, bk = blockIdx.x;
    if (bk < 128) {
        float s = 0.f;
        #pragma unroll 4
        for (int d = tid; d < D_DIM; d += 256)
            s += Wo[bk * D_DIM + d] * Wp[d];
        red[tid] = s; __syncthreads();
        for (int off = 128; off > 0; off >>= 1) {
            if (tid < off) red[tid] += red[tid + off];
            __syncthreads();
        }
        if (tid == 0) g_u[bk] = red[0];
    } else if (bk < 144) {
        int c = bk - 128;
        float s = 0.f;
        #pragma unroll 4
        for (int q = 0; q < 128; q++) {
            int d = c * 128 + q;
            s += W1[(long long)d * H1 + tid] * Wp[d];
        }
        g_wpart[c][tid] = s;
    } else if (bk < 160) {
        int base = (bk - 144) * 2048;
        for (int e = base + tid; e < base + 2048; e += 256) {
            int i = e >> 7, jq = e & 127;
            g_W2T[jq * H1 + i] = W2[e];
        }
    } else {
        size_t i = ((size_t)(bk - 160) * 256 + tid) * 8;   // Wo [128 x 2048]
        float4 v0 = *(const float4*)(Wo + i);
        float4 v1 = *(const float4*)(Wo + i + 4);
        uint32_t h[4], m[4];
        split2(v0.x, v0.y, h[0], m[0]);
        split2(v0.z, v0.w, h[1], m[1]);
        split2(v1.x, v1.y, h[2], m[2]);
        split2(v1.z, v1.w, h[3], m[3]);
        size_t off = (size_t)256 * D_DIM + i;
        *(uint4*)(g_Bbf + off)           = make_uint4(h[0], h[1], h[2], h[3]);
        *(uint4*)(g_Bbf + B_PLANE + off) = make_uint4(m[0], m[1], m[2], m[3]);
    }
}

__global__ void reduce_w_kernel() {
    int i = threadIdx.x;
    float s = 0.f;
    #pragma unroll
    for (int c = 0; c < 16; c++) s += g_wpart[c][i];
    g_w[i] = s;
}

// ============================================================
// gemm_a1 (round-11 body + m-offset): a1[m][n] = sum_k x[m][k] W1[k][n] + b1[n]
//   FFMA2, single fp32 accumulator per output, k strictly ascending —
//   rounding chain BIT-IDENTICAL to all passing kernels.
//   CTA 128m x 64n, 128 thr, 8x8 microtile, 4-stage.
//   Launched as two halves: grid (32,4), m_base = 0 / B/2.
// ============================================================
#define AM 128
#define AN 64
#define AK 16
static constexpr int A_PITCH = 80;
static constexpr int A_BOFF  = AM * A_PITCH;          // 10240
static constexpr int A_STG_B = A_BOFF + AN * AK * 4;  // 14336
static constexpr int A_SMEM  = 4 * A_STG_B;           // 57344

__device__ __forceinline__ void a1_load(uint32_t sb, int s, const float* __restrict__ X,
                                        const float* __restrict__ W1,
                                        int m0, int n0, int k0, int tid) {
    uint32_t base = sb + s * A_STG_B;
    #pragma unroll
    for (int q = 0; q < 4; q++) {
        int idx = q * 128 + tid;
        int row = idx >> 2, seg = idx & 3;
        cpa16(base + row * A_PITCH + seg * 16,
              X + (size_t)(m0 + row) * D_DIM + k0 + seg * 4);
    }
    #pragma unroll
    for (int q = 0; q < 2; q++) {
        int idx = q * 128 + tid;
        int kk = idx >> 4, seg = idx & 15;
        cpa16(base + A_BOFF + kk * 256 + seg * 16,
              W1 + (size_t)(k0 + kk) * H1 + n0 + seg * 4);
    }
    asm volatile("cp.async.commit_group;" ::: "memory");
}

__global__ __launch_bounds__(128) void gemm_a1(const float* __restrict__ X,
                                               const float* __restrict__ W1,
                                               const float* __restrict__ b1,
                                               int m_base) {
    extern __shared__ char smem[];
    uint32_t sb = s2u(smem);
    int tid = threadIdx.x, wid = tid >> 5, lid = tid & 31;
    int m0 = m_base + blockIdx.x * AM, n0 = blockIdx.y * AN;
    int wm = (wid & 1) * 64, wn = (wid >> 1) * 32;
    int r = lid >> 2, cg = lid & 3;

    ull acc[2][4][4];
    #pragma unroll
    for (int h = 0; h < 2; h++)
        #pragma unroll
        for (int b = 0; b < 4; b++)
            #pragma unroll
            for (int j = 0; j < 4; j++) acc[h][b][j] = 0ull;

    a1_load(sb, 0, X, W1, m0, n0, 0,      tid);
    a1_load(sb, 1, X, W1, m0, n0, AK,     tid);
    a1_load(sb, 2, X, W1, m0, n0, 2 * AK, tid);

    const int NITER = D_DIM / AK;   // 128
    for (int i = 0; i < NITER; i++) {
        int s = i & 3;
        asm volatile("cp.async.wait_group %0;" :: "n"(2) : "memory");
        __syncthreads();
        if (i + 3 < NITER) a1_load(sb, (i + 3) & 3, X, W1, m0, n0, (i + 3) * AK, tid);
        else asm volatile("cp.async.commit_group;" ::: "memory");

        const char* stg = smem + s * A_STG_B;
        #pragma unroll
        for (int g = 0; g < 4; g++) {
            float4 av[2][4];
            #pragma unroll
            for (int h = 0; h < 2; h++)
                #pragma unroll
                for (int b = 0; b < 4; b++)
                    av[h][b] = *(const float4*)(stg + (wm + h * 32 + 8 * b + r) * A_PITCH + g * 16);
            #pragma unroll
            for (int c = 0; c < 4; c++) {        // k = 16i + 4g + c, ascending
                int kk = g * 4 + c;
                ulonglong2 bA = *(const ulonglong2*)(stg + A_BOFF + kk * 256 + (wn + 4 * cg) * 4);
                ulonglong2 bB = *(const ulonglong2*)(stg + A_BOFF + kk * 256 + (wn + 16 + 4 * cg) * 4);
                #pragma unroll
                for (int b = 0; b < 4; b++) {
                    ull a0 = dup2(((const float*)&av[0][b])[c]);
                    ull a1d = dup2(((const float*)&av[1][b])[c]);
                    fma2(acc[0][b][0], a0,  bA.x); fma2(acc[0][b][1], a0,  bA.y);
                    fma2(acc[0][b][2], a0,  bB.x); fma2(acc[0][b][3], a0,  bB.y);
                    fma2(acc[1][b][0], a1d, bA.x); fma2(acc[1][b][1], a1d, bA.y);
                    fma2(acc[1][b][2], a1d, bB.x); fma2(acc[1][b][3], a1d, bB.y);
                }
            }
        }
    }

    #pragma unroll
    for (int h = 0; h < 2; h++)
        #pragma unroll
        for (int b = 0; b < 4; b++) {
            size_t M = (size_t)(m0 + wm + h * 32 + 8 * b + r);
            float* dst = g_scratch + M * NB + n0 + wn;
            #pragma unroll
            for (int j = 0; j < 4; j++) {
                int nc = (j >> 1) * 16 + 4 * cg + (j & 1) * 2;
                float2 v = unpack2(acc[h][b][j]);
                v.x += b1[n0 + wn + nc];
                v.y += b1[n0 + wn + nc + 1];
                *(float2*)(dst + nc) = v;
            }
        }
}

// ============================================================
// gemm_g2 (round-15 verbatim): split-K 2-way, part0 -> g_scratch,
// part1 -> g_g2p. grid (B/64, 2) = 256 CTAs.
// ============================================================
#define BM 64
#define BN 128
#define KC 16
static constexpr int GB_OFF  = BM * KC * 4;               // 4096
static constexpr int G_STG   = GB_OFF + 2 * BN * KC * 2;  // 12288
static constexpr int G_SMEM  = 4 * G_STG;                 // 49152

__device__ __forceinline__ void g2_load(uint32_t sb, int s, const float* __restrict__ X,
                                        int m0, int k0, int tid) {
    uint32_t base = sb + s * G_STG;
    #pragma unroll
    for (int q = 0; q < 2; q++) {
        int idx = q * 128 + tid;
        int row = idx >> 2, seg = idx & 3;
        cpa16(base + row * 64 + seg * 16,
              X + (size_t)(m0 + row) * D_DIM + k0 + seg * 4);
    }
    #pragma unroll
    for (int q = 0; q < 4; q++) {
        int i = q * 128 + tid;
        int plane = i >> 8, rem = i & 255, row = rem >> 1, half = rem & 1;
        cpa16(base + GB_OFF + plane * 4096 + row * 32 + half * 16,
              g_Bbf + (size_t)plane * B_PLANE + (size_t)(256 + row) * D_DIM + k0 + half * 8);
    }
    asm volatile("cp.async.commit_group;" ::: "memory");
}

__global__ __launch_bounds__(128) void gemm_g2(const float* __restrict__ X) {
    extern __shared__ char smem[];
    uint32_t sb = s2u(smem);
    int tid = threadIdx.x, wid = tid >> 5, lid = tid & 31;
    int m0 = blockIdx.x * BM;
    int kb = blockIdx.y * 1024;          // K half base
    int warp_m = (wid & 1) * 32, warp_n = (wid >> 1) * 64;
    int rr = lid >> 2, cc = lid & 3;

    float c[2][8][4];
    #pragma unroll
    for (int mf = 0; mf < 2; mf++)
        #pragma unroll
        for (int nf = 0; nf < 8; nf++)
            #pragma unroll
            for (int q = 0; q < 4; q++) c[mf][nf][q] = 0.f;

    g2_load(sb, 0, X, m0, kb,          tid);
    g2_load(sb, 1, X, m0, kb + KC,     tid);
    g2_load(sb, 2, X, m0, kb + 2 * KC, tid);

    const int NITER = 1024 / KC;   // 64
    for (int i = 0; i < NITER; i++) {
        int s = i & 3;
        asm volatile("cp.async.wait_group %0;" :: "n"(2) : "memory");
        __syncthreads();
        if (i + 3 < NITER) g2_load(sb, (i + 3) & 3, X, m0, kb + (i + 3) * KC, tid);
        else asm volatile("cp.async.commit_group;" ::: "memory");

        const char* stg = smem + s * G_STG;

        uint2 Af[2][2][2];
        #pragma unroll
        for (int mf = 0; mf < 2; mf++)
            #pragma unroll
            for (int j = 0; j < 2; j++) {
                float4 v = *(const float4*)(stg + (warp_m + mf * 16 + j * 8 + rr) * 64 + cc * 16);
                uint32_t h0, m0_, h1, m1_;
                split2(v.x, v.y, h0, m0_);
                split2(v.z, v.w, h1, m1_);
                Af[0][mf][j] = make_uint2(h0, h1);
                Af[1][mf][j] = make_uint2(m0_, m1_);
            }

        #pragma unroll
        for (int hh = 0; hh < 2; hh++) {
            uint2 Bf[2][4];
            #pragma unroll
            for (int p = 0; p < 2; p++)
                #pragma unroll
                for (int nf = 0; nf < 4; nf++)
                    Bf[p][nf] = *(const uint2*)(stg + GB_OFF + p * 4096 +
                                                (warp_n + (hh * 4 + nf) * 8 + rr) * 32 + cc * 8);
            #pragma unroll
            for (int nf = 0; nf < 4; nf++) {
                int nn = hh * 4 + nf;
                #pragma unroll
                for (int mf = 0; mf < 2; mf++) {
                    float* cp = c[mf][nn];
                    mma16(cp, Af[0][mf], Bf[0][nf]);   // h*h
                    mma16(cp, Af[0][mf], Bf[1][nf]);   // h*m
                    mma16(cp, Af[1][mf], Bf[0][nf]);   // m*h
                }
            }
        }
    }

    bool p0 = (blockIdx.y == 0);
    #pragma unroll
    for (int mf = 0; mf < 2; mf++) {
        int mA = m0 + warp_m + mf * 16 + rr;
        #pragma unroll
        for (int nf = 0; nf < 8; nf++) {
            int n = warp_n + nf * 8 + 2 * cc;
            float2 v0 = { c[mf][nf][0], c[mf][nf][1] };
            float2 v1 = { c[mf][nf][2], c[mf][nf][3] };
            if (p0) {
                *(float2*)&g_scratch[(size_t)mA * NB + 256 + n]       = v0;
                *(float2*)&g_scratch[(size_t)(mA + 8) * NB + 256 + n] = v1;
            } else {
                *(float2*)&g_g2p[(size_t)mA * H2 + n]       = v0;
                *(float2*)&g_g2p[(size_t)(mA + 8) * H2 + n] = v1;
            }
        }
    }
}

// ============================================================
// Epilogue v2 (round-15 chains; g2 = part0 + part1; sample base arg)
// ============================================================
__global__ __launch_bounds__(256) void epilogue_kernel(
    const float* __restrict__ b1, const float* __restrict__ W2,
    const float* __restrict__ b2, const float* __restrict__ bp,
    float* __restrict__ out, int s_base)
{
    __shared__ float h1s[H1][16];
    __shared__ float th1s[H1][16];
    __shared__ float gh2s[H2][16];
    __shared__ float wsum[8][8];

    int tid = threadIdx.x;
    int jh  = tid & 127;
    int sh  = tid >> 7;
    int sg  = sh * 8;
    int b0  = s_base + blockIdx.x * 16;

    for (int idx = tid; idx < 16 * H1; idx += 256) {
        int s = idx >> 8, i = idx & 255;
        float a = g_scratch[(size_t)(b0 + s) * NB + i];
        bool m = a > 0.f;
        h1s[i][s]  = m ? a : 0.f;
        th1s[i][s] = m ? (a - b1[i]) : 0.f;
    }
    __syncthreads();

    ull accA[4], accT[4];
    ull bd = dup2(b2[jh]);
    #pragma unroll
    for (int p = 0; p < 4; p++) { accA[p] = bd; accT[p] = 0ull; }
    #pragma unroll 4
    for (int i = 0; i < H1; i++) {
        ull wd = dup2(W2[i * H2 + jh]);
        ulonglong2 h01 = *(const ulonglong2*)&h1s[i][sg];
        ulonglong2 h23 = *(const ulonglong2*)&h1s[i][sg + 4];
        ulonglong2 t01 = *(const ulonglong2*)&th1s[i][sg];
        ulonglong2 t23 = *(const ulonglong2*)&th1s[i][sg + 4];
        fma2(accA[0], wd, h01.x); fma2(accA[1], wd, h01.y);
        fma2(accA[2], wd, h23.x); fma2(accA[3], wd, h23.y);
        fma2(accT[0], wd, t01.x); fma2(accT[1], wd, t01.y);
        fma2(accT[2], wd, t23.x); fma2(accT[3], wd, t23.y);
    }
    float pr[8];
    float uj = g_u[jh];
    #pragma unroll
    for (int p = 0; p < 4; p++) {
        float2 a2 = unpack2(accA[p]);
        float2 t2 = unpack2(accT[p]);
        bool ma = a2.x > 0.f, mb2 = a2.y > 0.f;
        float gva = g_scratch[(size_t)(b0 + sg + 2 * p)     * NB + H1 + jh]
                  + g_g2p[(size_t)(b0 + sg + 2 * p)     * H2 + jh];
        float gvb = g_scratch[(size_t)(b0 + sg + 2 * p + 1) * NB + H1 + jh]
                  + g_g2p[(size_t)(b0 + sg + 2 * p + 1) * H2 + jh];
        pr[2 * p]     = ma  ? t2.x * uj : 0.f;
        pr[2 * p + 1] = mb2 ? t2.y * uj : 0.f;
        gh2s[jh][sg + 2 * p]     = ma  ? gva : 0.f;
        gh2s[jh][sg + 2 * p + 1] = mb2 ? gvb : 0.f;
    }
    __syncthreads();

    int i0 = jh, i1 = jh + 128;
    ull gA2[4] = {0,0,0,0}, gB2[4] = {0,0,0,0};
    #pragma unroll 4
    for (int jj = 0; jj < H2; jj++) {
        ull w0 = dup2(g_W2T[jj * H1 + i0]);
        ull w1 = dup2(g_W2T[jj * H1 + i1]);
        ulonglong2 g01 = *(const ulonglong2*)&gh2s[jj][sg];
        ulonglong2 g23 = *(const ulonglong2*)&gh2s[jj][sg + 4];
        fma2(gA2[0], w0, g01.x); fma2(gA2[1], w0, g01.y);
        fma2(gA2[2], w0, g23.x); fma2(gA2[3], w0, g23.y);
        fma2(gB2[0], w1, g01.x); fma2(gB2[1], w1, g01.y);
        fma2(gB2[2], w1, g23.x); fma2(gB2[3], w1, g23.y);
    }
    float wi0 = g_w[i0], wi1 = g_w[i1];
    #pragma unroll
    for (int p = 0; p < 4; p++) {
        float2 ga = unpack2(gA2[p]);
        float2 gb = unpack2(gB2[p]);
        float jt0 = 0.f, jt1 = 0.f;
        if (h1s[i0][sg + 2 * p] > 0.f)     jt0 += ga.x * wi0;
        if (h1s[i1][sg + 2 * p] > 0.f)     jt0 += gb.x * wi1;
        if (h1s[i0][sg + 2 * p + 1] > 0.f) jt1 += ga.y * wi0;
        if (h1s[i1][sg + 2 * p + 1] > 0.f) jt1 += gb.y * wi1;
        pr[2 * p]     -= jt0;
        pr[2 * p + 1] -= jt1;
    }

    int lane = tid & 31, wpi = tid >> 5;
    #pragma unroll
    for (int sp = 0; sp < 8; sp++) {
        float v = pr[sp];
        #pragma unroll
        for (int off = 16; off > 0; off >>= 1)
            v += __shfl_xor_sync(0xffffffffu, v, off);
        if (lane == 0) wsum[wpi][sp] = v;
    }
    __syncthreads();
    if (tid < 16) {
        int shh = tid >> 3, sp = tid & 7;
        out[b0 + tid] = wsum[4 * shh + 0][sp] + wsum[4 * shh + 1][sp] +
                        wsum[4 * shh + 2][sp] + wsum[4 * shh + 3][sp] + bp[0];
    }
}

// ============================================================
// launch — pipelined tail: a1 in two m-halves on priority stream;
// epilogue half launches as soon as its a1 half completes.
// ============================================================
extern "C" void kernel_launch(void* const* d_in, const int* in_sizes, int n_in,
                              void* d_out, int out_size) {
    const float* x  = (const float*)d_in[0];
    const float* W1 = (const float*)d_in[1];
    const float* b1 = (const float*)d_in[2];
    const float* W2 = (const float*)d_in[3];
    const float* b2 = (const float*)d_in[4];
    const float* Wo = (const float*)d_in[5];
    const float* Wp = (const float*)d_in[7];
    const float* bp = (const float*)d_in[8];

    int B  = in_sizes[0] / D_DIM;   // 8192
    int Bh = B / 2;                 // 4096

    static cudaStream_t s_side = nullptr;
    static cudaEvent_t ev_fork = nullptr, ev_h0 = nullptr, ev_h1 = nullptr;
    if (s_side == nullptr) {
        int lo, hi;
        cudaDeviceGetStreamPriorityRange(&lo, &hi);
        cudaStreamCreateWithPriority(&s_side, cudaStreamNonBlocking, hi);
        cudaEventCreateWithFlags(&ev_fork, cudaEventDisableTiming);
        cudaEventCreateWithFlags(&ev_h0, cudaEventDisableTiming);
        cudaEventCreateWithFlags(&ev_h1, cudaEventDisableTiming);
        cudaFuncSetAttribute(gemm_a1, cudaFuncAttributeMaxDynamicSharedMemorySize, A_SMEM);
        cudaFuncSetAttribute(gemm_g2, cudaFuncAttributeMaxDynamicSharedMemorySize, G_SMEM);
    }

    // fork: a1 halves on highest-priority side stream
    cudaEventRecord(ev_fork, 0);
    cudaStreamWaitEvent(s_side, ev_fork, 0);
    gemm_a1<<<dim3(Bh / AM, 4), 128, A_SMEM, s_side>>>(x, W1, b1, 0);
    cudaEventRecord(ev_h0, s_side);
    gemm_a1<<<dim3(Bh / AM, 4), 128, A_SMEM, s_side>>>(x, W1, b1, Bh);
    cudaEventRecord(ev_h1, s_side);

    // main: preps then g2 (needs g_Bbf), split-K 2-way
    prep_misc<<<288, 256>>>(W1, W2, Wo, Wp);
    reduce_w_kernel<<<1, 256>>>();
    gemm_g2<<<dim3(B / BM, 2), 128, G_SMEM>>>(x);

    // epilogue half 0 as soon as a1 half 0 done (g2 ordered on main stream)
    cudaStreamWaitEvent(0, ev_h0, 0);
    epilogue_kernel<<<Bh / 16, 256>>>(b1, W2, b2, bp, (float*)d_out, 0);

    // epilogue half 1 after a1 half 1
    cudaStreamWaitEvent(0, ev_h1, 0);
    epilogue_kernel<<<Bh / 16, 256>>>(b1, W2, b2, bp, (float*)d_out, Bh);
}

// round 17
// speedup vs baseline: 1.3055x; 1.3055x over previous
#include <cuda_runtime.h>
#include <cuda_bf16.h>
#include <cstdint>

typedef unsigned long long ull;

#define D_DIM 2048
#define H1 256
#define H2 128
#define NB  384
#define MAX_B 8192

static constexpr size_t B_PLANE = (size_t)NB * D_DIM;

// ---------------- device scratch ----------------
__device__ uint16_t g_Bbf[2 * B_PLANE];            // bf16 planes h,m; rows 256..383 (Wo) used
__device__ float    g_scratch[(size_t)MAX_B * NB]; // [a1(256) | g2 part0(128)]
__device__ float    g_g2p[(size_t)MAX_B * H2];     // g2 part1 (K upper half)
__device__ float    g_u[H2];
__device__ float    g_w[H1];
__device__ float    g_wpart[16][H1];
__device__ float    g_W2T[H2 * H1];

// ---------------- helpers ----------------
__device__ __forceinline__ ull dup2(float x) {
    ull r; asm("mov.b64 %0, {%1, %1};" : "=l"(r) : "f"(x)); return r;
}
__device__ __forceinline__ void fma2(ull &d, ull a, ull b) {
    asm("fma.rn.f32x2 %0, %1, %2, %0;" : "+l"(d) : "l"(a), "l"(b));
}
__device__ __forceinline__ float2 unpack2(ull v) {
    float2 f; asm("mov.b64 {%0, %1}, %2;" : "=f"(f.x), "=f"(f.y) : "l"(v)); return f;
}
__device__ __forceinline__ void cpa16(uint32_t dst, const void* src) {
    asm volatile("cp.async.cg.shared.global [%0], [%1], 16;\n" :: "r"(dst), "l"(src));
}
__device__ __forceinline__ uint32_t s2u(const void* p) {
    uint32_t r; asm("{ .reg .u64 t; cvta.to.shared.u64 t, %1; cvt.u32.u64 %0, t; }" : "=r"(r) : "l"(p)); return r;
}
__device__ __forceinline__ uint32_t packbf(float hi, float lo) {
    uint32_t r; asm("cvt.rn.bf16x2.f32 %0, %1, %2;" : "=r"(r) : "f"(hi), "f"(lo)); return r;
}
__device__ __forceinline__ float bfhi(uint32_t v) { return __uint_as_float(v & 0xFFFF0000u); }
__device__ __forceinline__ float bflo(uint32_t v) { return __uint_as_float(v << 16); }

// 2-way bf16 split of a pair (a = even-k -> lo half, b = odd-k -> hi half)
__device__ __forceinline__ void split2(float a, float b, uint32_t &h, uint32_t &m) {
    h = packbf(b, a);
    float ra = a - bflo(h), rb = b - bfhi(h);
    m = packbf(rb, ra);
}

__device__ __forceinline__ void mma16(float* c, const uint2* A, uint2 b) {
    asm volatile(
        "mma.sync.aligned.m16n8k16.row.col.f32.bf16.bf16.f32 "
        "{%0,%1,%2,%3}, {%4,%5,%6,%7}, {%8,%9}, {%0,%1,%2,%3};"
        : "+f"(c[0]), "+f"(c[1]), "+f"(c[2]), "+f"(c[3])
        : "r"(A[0].x), "r"(A[1].x), "r"(A[0].y), "r"(A[1].y), "r"(b.x), "r"(b.y));
}

// ============================================================
// prep_misc: u = Wo@Wp (bk<128), wpart (bk<144), W2T (bk<160),
//            Wo bf16 planes h,m (bk 160..287). grid 288 x 256
// ============================================================
__global__ __launch_bounds__(256) void prep_misc(
    const float* __restrict__ W1, const float* __restrict__ W2,
    const float* __restrict__ Wo, const float* __restrict__ Wp)
{
    __shared__ float red[256];
    int tid = threadIdx.x, bk = blockIdx.x;
    if (bk < 128) {
        float s = 0.f;
        #pragma unroll 4
        for (int d = tid; d < D_DIM; d += 256)
            s += Wo[bk * D_DIM + d] * Wp[d];
        red[tid] = s; __syncthreads();
        for (int off = 128; off > 0; off >>= 1) {
            if (tid < off) red[tid] += red[tid + off];
            __syncthreads();
        }
        if (tid == 0) g_u[bk] = red[0];
    } else if (bk < 144) {
        int c = bk - 128;
        float s = 0.f;
        #pragma unroll 4
        for (int q = 0; q < 128; q++) {
            int d = c * 128 + q;
            s += W1[(long long)d * H1 + tid] * Wp[d];
        }
        g_wpart[c][tid] = s;
    } else if (bk < 160) {
        int base = (bk - 144) * 2048;
        for (int e = base + tid; e < base + 2048; e += 256) {
            int i = e >> 7, jq = e & 127;
            g_W2T[jq * H1 + i] = W2[e];
        }
    } else {
        size_t i = ((size_t)(bk - 160) * 256 + tid) * 8;   // Wo [128 x 2048]
        float4 v0 = *(const float4*)(Wo + i);
        float4 v1 = *(const float4*)(Wo + i + 4);
        uint32_t h[4], m[4];
        split2(v0.x, v0.y, h[0], m[0]);
        split2(v0.z, v0.w, h[1], m[1]);
        split2(v1.x, v1.y, h[2], m[2]);
        split2(v1.z, v1.w, h[3], m[3]);
        size_t off = (size_t)256 * D_DIM + i;
        *(uint4*)(g_Bbf + off)           = make_uint4(h[0], h[1], h[2], h[3]);
        *(uint4*)(g_Bbf + B_PLANE + off) = make_uint4(m[0], m[1], m[2], m[3]);
    }
}

__global__ void reduce_w_kernel() {
    int i = threadIdx.x;
    float s = 0.f;
    #pragma unroll
    for (int c = 0; c < 16; c++) s += g_wpart[c][i];
    g_w[i] = s;
}

// ============================================================
// gemm_a1 (round-11 body, 5-stage pipeline):
//   a1[m][n] = sum_k x[m][k] W1[k][n] + b1[n]
//   FFMA2, single fp32 accumulator per output, k strictly ascending —
//   rounding chain BIT-IDENTICAL to all passing kernels.
//   CTA 128m x 64n, 128 thr, 8x8 microtile. grid (64,4) = 256 (single wave).
// ============================================================
#define AM 128
#define AN 64
#define AK 16
#define A_NSTG 5
static constexpr int A_PITCH = 80;
static constexpr int A_BOFF  = AM * A_PITCH;          // 10240
static constexpr int A_STG_B = A_BOFF + AN * AK * 4;  // 14336
static constexpr int A_SMEM  = A_NSTG * A_STG_B;      // 71680

__device__ __forceinline__ void a1_load(uint32_t sb, int s, const float* __restrict__ X,
                                        const float* __restrict__ W1,
                                        int m0, int n0, int k0, int tid) {
    uint32_t base = sb + s * A_STG_B;
    #pragma unroll
    for (int q = 0; q < 4; q++) {
        int idx = q * 128 + tid;
        int row = idx >> 2, seg = idx & 3;
        cpa16(base + row * A_PITCH + seg * 16,
              X + (size_t)(m0 + row) * D_DIM + k0 + seg * 4);
    }
    #pragma unroll
    for (int q = 0; q < 2; q++) {
        int idx = q * 128 + tid;
        int kk = idx >> 4, seg = idx & 15;
        cpa16(base + A_BOFF + kk * 256 + seg * 16,
              W1 + (size_t)(k0 + kk) * H1 + n0 + seg * 4);
    }
    asm volatile("cp.async.commit_group;" ::: "memory");
}

__global__ __launch_bounds__(128) void gemm_a1(const float* __restrict__ X,
                                               const float* __restrict__ W1,
                                               const float* __restrict__ b1) {
    extern __shared__ char smem[];
    uint32_t sb = s2u(smem);
    int tid = threadIdx.x, wid = tid >> 5, lid = tid & 31;
    int m0 = blockIdx.x * AM, n0 = blockIdx.y * AN;
    int wm = (wid & 1) * 64, wn = (wid >> 1) * 32;
    int r = lid >> 2, cg = lid & 3;

    ull acc[2][4][4];
    #pragma unroll
    for (int h = 0; h < 2; h++)
        #pragma unroll
        for (int b = 0; b < 4; b++)
            #pragma unroll
            for (int j = 0; j < 4; j++) acc[h][b][j] = 0ull;

    // prologue: stages 0..3
    a1_load(sb, 0, X, W1, m0, n0, 0,      tid);
    a1_load(sb, 1, X, W1, m0, n0, AK,     tid);
    a1_load(sb, 2, X, W1, m0, n0, 2 * AK, tid);
    a1_load(sb, 3, X, W1, m0, n0, 3 * AK, tid);

    const int NITER = D_DIM / AK;   // 128
    int s = 0;
    for (int i = 0; i < NITER; i++) {
        asm volatile("cp.async.wait_group %0;" :: "n"(3) : "memory");
        __syncthreads();
        if (i + 4 < NITER) {
            int sl = s + 4; if (sl >= A_NSTG) sl -= A_NSTG;   // == (i-1)%5, consumed last iter
            a1_load(sb, sl, X, W1, m0, n0, (i + 4) * AK, tid);
        } else {
            asm volatile("cp.async.commit_group;" ::: "memory");
        }

        const char* stg = smem + s * A_STG_B;
        #pragma unroll
        for (int g = 0; g < 4; g++) {
            float4 av[2][4];
            #pragma unroll
            for (int h = 0; h < 2; h++)
                #pragma unroll
                for (int b = 0; b < 4; b++)
                    av[h][b] = *(const float4*)(stg + (wm + h * 32 + 8 * b + r) * A_PITCH + g * 16);
            #pragma unroll
            for (int c = 0; c < 4; c++) {        // k = 16i + 4g + c, ascending
                int kk = g * 4 + c;
                ulonglong2 bA = *(const ulonglong2*)(stg + A_BOFF + kk * 256 + (wn + 4 * cg) * 4);
                ulonglong2 bB = *(const ulonglong2*)(stg + A_BOFF + kk * 256 + (wn + 16 + 4 * cg) * 4);
                #pragma unroll
                for (int b = 0; b < 4; b++) {
                    ull a0 = dup2(((const float*)&av[0][b])[c]);
                    ull a1d = dup2(((const float*)&av[1][b])[c]);
                    fma2(acc[0][b][0], a0,  bA.x); fma2(acc[0][b][1], a0,  bA.y);
                    fma2(acc[0][b][2], a0,  bB.x); fma2(acc[0][b][3], a0,  bB.y);
                    fma2(acc[1][b][0], a1d, bA.x); fma2(acc[1][b][1], a1d, bA.y);
                    fma2(acc[1][b][2], a1d, bB.x); fma2(acc[1][b][3], a1d, bB.y);
                }
            }
        }
        if (++s == A_NSTG) s = 0;
    }

    #pragma unroll
    for (int h = 0; h < 2; h++)
        #pragma unroll
        for (int b = 0; b < 4; b++) {
            size_t M = (size_t)(m0 + wm + h * 32 + 8 * b + r);
            float* dst = g_scratch + M * NB + n0 + wn;
            #pragma unroll
            for (int j = 0; j < 4; j++) {
                int nc = (j >> 1) * 16 + 4 * cg + (j & 1) * 2;
                float2 v = unpack2(acc[h][b][j]);
                v.x += b1[n0 + wn + nc];
                v.y += b1[n0 + wn + nc + 1];
                *(float2*)(dst + nc) = v;
            }
        }
}

// ============================================================
// gemm_g2 (round-15 verbatim): split-K 2-way, part0 -> g_scratch,
// part1 -> g_g2p. grid (B/64, 2) = 256 CTAs.
// ============================================================
#define BM 64
#define BN 128
#define KC 16
static constexpr int GB_OFF  = BM * KC * 4;               // 4096
static constexpr int G_STG   = GB_OFF + 2 * BN * KC * 2;  // 12288
static constexpr int G_SMEM  = 4 * G_STG;                 // 49152

__device__ __forceinline__ void g2_load(uint32_t sb, int s, const float* __restrict__ X,
                                        int m0, int k0, int tid) {
    uint32_t base = sb + s * G_STG;
    #pragma unroll
    for (int q = 0; q < 2; q++) {
        int idx = q * 128 + tid;
        int row = idx >> 2, seg = idx & 3;
        cpa16(base + row * 64 + seg * 16,
              X + (size_t)(m0 + row) * D_DIM + k0 + seg * 4);
    }
    #pragma unroll
    for (int q = 0; q < 4; q++) {
        int i = q * 128 + tid;
        int plane = i >> 8, rem = i & 255, row = rem >> 1, half = rem & 1;
        cpa16(base + GB_OFF + plane * 4096 + row * 32 + half * 16,
              g_Bbf + (size_t)plane * B_PLANE + (size_t)(256 + row) * D_DIM + k0 + half * 8);
    }
    asm volatile("cp.async.commit_group;" ::: "memory");
}

__global__ __launch_bounds__(128) void gemm_g2(const float* __restrict__ X) {
    extern __shared__ char smem[];
    uint32_t sb = s2u(smem);
    int tid = threadIdx.x, wid = tid >> 5, lid = tid & 31;
    int m0 = blockIdx.x * BM;
    int kb = blockIdx.y * 1024;          // K half base
    int warp_m = (wid & 1) * 32, warp_n = (wid >> 1) * 64;
    int rr = lid >> 2, cc = lid & 3;

    float c[2][8][4];
    #pragma unroll
    for (int mf = 0; mf < 2; mf++)
        #pragma unroll
        for (int nf = 0; nf < 8; nf++)
            #pragma unroll
            for (int q = 0; q < 4; q++) c[mf][nf][q] = 0.f;

    g2_load(sb, 0, X, m0, kb,          tid);
    g2_load(sb, 1, X, m0, kb + KC,     tid);
    g2_load(sb, 2, X, m0, kb + 2 * KC, tid);

    const int NITER = 1024 / KC;   // 64
    for (int i = 0; i < NITER; i++) {
        int s = i & 3;
        asm volatile("cp.async.wait_group %0;" :: "n"(2) : "memory");
        __syncthreads();
        if (i + 3 < NITER) g2_load(sb, (i + 3) & 3, X, m0, kb + (i + 3) * KC, tid);
        else asm volatile("cp.async.commit_group;" ::: "memory");

        const char* stg = smem + s * G_STG;

        uint2 Af[2][2][2];
        #pragma unroll
        for (int mf = 0; mf < 2; mf++)
            #pragma unroll
            for (int j = 0; j < 2; j++) {
                float4 v = *(const float4*)(stg + (warp_m + mf * 16 + j * 8 + rr) * 64 + cc * 16);
                uint32_t h0, m0_, h1, m1_;
                split2(v.x, v.y, h0, m0_);
                split2(v.z, v.w, h1, m1_);
                Af[0][mf][j] = make_uint2(h0, h1);
                Af[1][mf][j] = make_uint2(m0_, m1_);
            }

        #pragma unroll
        for (int hh = 0; hh < 2; hh++) {
            uint2 Bf[2][4];
            #pragma unroll
            for (int p = 0; p < 2; p++)
                #pragma unroll
                for (int nf = 0; nf < 4; nf++)
                    Bf[p][nf] = *(const uint2*)(stg + GB_OFF + p * 4096 +
                                                (warp_n + (hh * 4 + nf) * 8 + rr) * 32 + cc * 8);
            #pragma unroll
            for (int nf = 0; nf < 4; nf++) {
                int nn = hh * 4 + nf;
                #pragma unroll
                for (int mf = 0; mf < 2; mf++) {
                    float* cp = c[mf][nn];
                    mma16(cp, Af[0][mf], Bf[0][nf]);   // h*h
                    mma16(cp, Af[0][mf], Bf[1][nf]);   // h*m
                    mma16(cp, Af[1][mf], Bf[0][nf]);   // m*h
                }
            }
        }
    }

    bool p0 = (blockIdx.y == 0);
    #pragma unroll
    for (int mf = 0; mf < 2; mf++) {
        int mA = m0 + warp_m + mf * 16 + rr;
        #pragma unroll
        for (int nf = 0; nf < 8; nf++) {
            int n = warp_n + nf * 8 + 2 * cc;
            float2 v0 = { c[mf][nf][0], c[mf][nf][1] };
            float2 v1 = { c[mf][nf][2], c[mf][nf][3] };
            if (p0) {
                *(float2*)&g_scratch[(size_t)mA * NB + 256 + n]       = v0;
                *(float2*)&g_scratch[(size_t)(mA + 8) * NB + 256 + n] = v1;
            } else {
                *(float2*)&g_g2p[(size_t)mA * H2 + n]       = v0;
                *(float2*)&g_g2p[(size_t)(mA + 8) * H2 + n] = v1;
            }
        }
    }
}

// ============================================================
// Epilogue v2 (round-15 verbatim; g2 = part0 + part1)
// ============================================================
__global__ __launch_bounds__(256) void epilogue_kernel(
    const float* __restrict__ b1, const float* __restrict__ W2,
    const float* __restrict__ b2, const float* __restrict__ bp,
    float* __restrict__ out)
{
    __shared__ float h1s[H1][16];
    __shared__ float th1s[H1][16];
    __shared__ float gh2s[H2][16];
    __shared__ float wsum[8][8];

    int tid = threadIdx.x;
    int jh  = tid & 127;
    int sh  = tid >> 7;
    int sg  = sh * 8;
    int b0  = blockIdx.x * 16;

    for (int idx = tid; idx < 16 * H1; idx += 256) {
        int s = idx >> 8, i = idx & 255;
        float a = g_scratch[(size_t)(b0 + s) * NB + i];
        bool m = a > 0.f;
        h1s[i][s]  = m ? a : 0.f;
        th1s[i][s] = m ? (a - b1[i]) : 0.f;
    }
    __syncthreads();

    ull accA[4], accT[4];
    ull bd = dup2(b2[jh]);
    #pragma unroll
    for (int p = 0; p < 4; p++) { accA[p] = bd; accT[p] = 0ull; }
    #pragma unroll 4
    for (int i = 0; i < H1; i++) {
        ull wd = dup2(W2[i * H2 + jh]);
        ulonglong2 h01 = *(const ulonglong2*)&h1s[i][sg];
        ulonglong2 h23 = *(const ulonglong2*)&h1s[i][sg + 4];
        ulonglong2 t01 = *(const ulonglong2*)&th1s[i][sg];
        ulonglong2 t23 = *(const ulonglong2*)&th1s[i][sg + 4];
        fma2(accA[0], wd, h01.x); fma2(accA[1], wd, h01.y);
        fma2(accA[2], wd, h23.x); fma2(accA[3], wd, h23.y);
        fma2(accT[0], wd, t01.x); fma2(accT[1], wd, t01.y);
        fma2(accT[2], wd, t23.x); fma2(accT[3], wd, t23.y);
    }
    float pr[8];
    float uj = g_u[jh];
    #pragma unroll
    for (int p = 0; p < 4; p++) {
        float2 a2 = unpack2(accA[p]);
        float2 t2 = unpack2(accT[p]);
        bool ma = a2.x > 0.f, mb2 = a2.y > 0.f;
        float gva = g_scratch[(size_t)(b0 + sg + 2 * p)     * NB + H1 + jh]
                  + g_g2p[(size_t)(b0 + sg + 2 * p)     * H2 + jh];
        float gvb = g_scratch[(size_t)(b0 + sg + 2 * p + 1) * NB + H1 + jh]
                  + g_g2p[(size_t)(b0 + sg + 2 * p + 1) * H2 + jh];
        pr[2 * p]     = ma  ? t2.x * uj : 0.f;
        pr[2 * p + 1] = mb2 ? t2.y * uj : 0.f;
        gh2s[jh][sg + 2 * p]     = ma  ? gva : 0.f;
        gh2s[jh][sg + 2 * p + 1] = mb2 ? gvb : 0.f;
    }
    __syncthreads();

    int i0 = jh, i1 = jh + 128;
    ull gA2[4] = {0,0,0,0}, gB2[4] = {0,0,0,0};
    #pragma unroll 4
    for (int jj = 0; jj < H2; jj++) {
        ull w0 = dup2(g_W2T[jj * H1 + i0]);
        ull w1 = dup2(g_W2T[jj * H1 + i1]);
        ulonglong2 g01 = *(const ulonglong2*)&gh2s[jj][sg];
        ulonglong2 g23 = *(const ulonglong2*)&gh2s[jj][sg + 4];
        fma2(gA2[0], w0, g01.x); fma2(gA2[1], w0, g01.y);
        fma2(gA2[2], w0, g23.x); fma2(gA2[3], w0, g23.y);
        fma2(gB2[0], w1, g01.x); fma2(gB2[1], w1, g01.y);
        fma2(gB2[2], w1, g23.x); fma2(gB2[3], w1, g23.y);
    }
    float wi0 = g_w[i0], wi1 = g_w[i1];
    #pragma unroll
    for (int p = 0; p < 4; p++) {
        float2 ga = unpack2(gA2[p]);
        float2 gb = unpack2(gB2[p]);
        float jt0 = 0.f, jt1 = 0.f;
        if (h1s[i0][sg + 2 * p] > 0.f)     jt0 += ga.x * wi0;
        if (h1s[i1][sg + 2 * p] > 0.f)     jt0 += gb.x * wi1;
        if (h1s[i0][sg + 2 * p + 1] > 0.f) jt1 += ga.y * wi0;
        if (h1s[i1][sg + 2 * p + 1] > 0.f) jt1 += gb.y * wi1;
        pr[2 * p]     -= jt0;
        pr[2 * p + 1] -= jt1;
    }

    int lane = tid & 31, wpi = tid >> 5;
    #pragma unroll
    for (int sp = 0; sp < 8; sp++) {
        float v = pr[sp];
        #pragma unroll
        for (int off = 16; off > 0; off >>= 1)
            v += __shfl_xor_sync(0xffffffffu, v, off);
        if (lane == 0) wsum[wpi][sp] = v;
    }
    __syncthreads();
    if (tid < 16) {
        int shh = tid >> 3, sp = tid & 7;
        out[b0 + tid] = wsum[4 * shh + 0][sp] + wsum[4 * shh + 1][sp] +
                        wsum[4 * shh + 2][sp] + wsum[4 * shh + 3][sp] + bp[0];
    }
}

// ============================================================
// launch — round-15 structure: a1 (single 256-CTA wave) on
// highest-priority side stream; prep + split-K g2 on main; join; epilogue.
// ============================================================
extern "C" void kernel_launch(void* const* d_in, const int* in_sizes, int n_in,
                              void* d_out, int out_size) {
    const float* x  = (const float*)d_in[0];
    const float* W1 = (const float*)d_in[1];
    const float* b1 = (const float*)d_in[2];
    const float* W2 = (const float*)d_in[3];
    const float* b2 = (const float*)d_in[4];
    const float* Wo = (const float*)d_in[5];
    const float* Wp = (const float*)d_in[7];
    const float* bp = (const float*)d_in[8];

    int B = in_sizes[0] / D_DIM;   // 8192

    static cudaStream_t s_side = nullptr;
    static cudaEvent_t ev_fork = nullptr, ev_join = nullptr;
    if (s_side == nullptr) {
        int lo, hi;
        cudaDeviceGetStreamPriorityRange(&lo, &hi);
        cudaStreamCreateWithPriority(&s_side, cudaStreamNonBlocking, hi);
        cudaEventCreateWithFlags(&ev_fork, cudaEventDisableTiming);
        cudaEventCreateWithFlags(&ev_join, cudaEventDisableTiming);
        cudaFuncSetAttribute(gemm_a1, cudaFuncAttributeMaxDynamicSharedMemorySize, A_SMEM);
        cudaFuncSetAttribute(gemm_g2, cudaFuncAttributeMaxDynamicSharedMemorySize, G_SMEM);
    }

    // fork: a1 depends only on x, W1, b1 — highest priority, ONE 256-CTA wave
    cudaEventRecord(ev_fork, 0);
    cudaStreamWaitEvent(s_side, ev_fork, 0);
    gemm_a1<<<dim3(B / AM, 4), 128, A_SMEM, s_side>>>(x, W1, b1);

    // main: preps then g2 (needs g_Bbf), split-K 2-way
    prep_misc<<<288, 256>>>(W1, W2, Wo, Wp);
    reduce_w_kernel<<<1, 256>>>();
    gemm_g2<<<dim3(B / BM, 2), 128, G_SMEM>>>(x);

    // join, then epilogue (needs a1 + both g2 parts)
    cudaEventRecord(ev_join, s_side);
    cudaStreamWaitEvent(0, ev_join, 0);
    epilogue_kernel<<<B / 16, 256>>>(b1, W2, b2, bp, (float*)d_out);
}